// round 2
// baseline (speedup 1.0000x reference)
#include <cuda_runtime.h>
#include <cstdint>

// Problem constants
#define HEADS   16
#define DHEAD   64
#define NSEQ    8192
#define EMB     1024
#define BATCH   2
#define CHUNK   128
#define NCHUNK  (NSEQ / CHUNK)          // 64
#define MROWS   (BATCH * NSEQ)          // 16384

// ---------------- scratch (device globals: allocation-free) ----------------
__device__ float g_q   [(size_t)BATCH * HEADS * NSEQ * DHEAD];   // 64 MB
__device__ float g_k   [(size_t)BATCH * HEADS * NSEQ * DHEAD];   // 64 MB
__device__ float g_v   [(size_t)BATCH * HEADS * NSEQ * DHEAD];   // 64 MB
__device__ float g_kvch[(size_t)BATCH * HEADS * NCHUNK * DHEAD * DHEAD]; // 32 MB
__device__ float g_kvpre[(size_t)BATCH * HEADS * NCHUNK * DHEAD * DHEAD];// 32 MB
__device__ float g_o   [(size_t)MROWS * EMB];                    // 64 MB
__device__ float g_g1  [(size_t)MROWS * DHEAD];                  // 4 MB
__device__ float g_gate[(size_t)MROWS * EMB];                    // 64 MB
__device__ float g_t   [(size_t)MROWS * EMB];                    // 64 MB

__device__ __forceinline__ float slope_s(int h) {
    // s[h] = 2^(-0.5*(h+1)) * (1 - layer/(L-1) + 1e-5), layer=0
    return exp2f(-0.5f * (float)(h + 1)) * (1.0f + 1e-5f);
}

// =====================================================================
// Generic 128x128x16 tiled SGEMM, 256 threads, 8x8 micro-tile,
// double-buffered shared memory (one barrier per K-step).
// EPI: 0 = plain store, 1 = silu + scatter to [b,h,n,d] (qkv, blockIdx.z
//      selects weight/output), 2 = sigmoid store.
// =====================================================================
template<int EPI>
__global__ void __launch_bounds__(256) sgemm_kernel(
    const float* __restrict__ A,
    const float* __restrict__ B0, const float* __restrict__ B1,
    const float* __restrict__ B2,
    float* __restrict__ O0, float* __restrict__ O1, float* __restrict__ O2,
    int M, int N, int K)
{
    const float* B = B0;
    float* O = O0;
    if (EPI == 1) {
        if (blockIdx.z == 1) { B = B1; O = O1; }
        else if (blockIdx.z == 2) { B = B2; O = O2; }
    }

    __shared__ float As[2][16][128];   // transposed A tile: As[buf][k][m]
    __shared__ float Bs[2][16][128];   // Bs[buf][k][n]

    const int tid = threadIdx.x;
    const int tx = tid & 15, ty = tid >> 4;
    const int m0 = blockIdx.y * 128, n0 = blockIdx.x * 128;

    // loader lane assignments (two 256-thread passes cover 512 float4s)
    const int lin1 = tid + 256;
    const int ra0 = tid  >> 2, ca0 = (tid  & 3) << 2;
    const int ra1 = lin1 >> 2, ca1 = (lin1 & 3) << 2;
    const int rb0 = tid  >> 5, cb0 = (tid  & 31) << 2;
    const int rb1 = lin1 >> 5, cb1 = (lin1 & 31) << 2;

    const float* Arow0 = A + (size_t)(m0 + ra0) * K;
    const float* Arow1 = A + (size_t)(m0 + ra1) * K;
    const float* Bp0   = B + (size_t)rb0 * N + n0 + cb0;
    const float* Bp1   = B + (size_t)rb1 * N + n0 + cb1;

    float acc[8][8];
#pragma unroll
    for (int i = 0; i < 8; i++)
#pragma unroll
        for (int j = 0; j < 8; j++) acc[i][j] = 0.f;

    // --- preload K-tile 0 into buffer 0 ---
    {
        float4 a0 = *(const float4*)(Arow0 + ca0);
        float4 a1 = *(const float4*)(Arow1 + ca1);
        float4 b0 = *(const float4*)(Bp0);
        float4 b1 = *(const float4*)(Bp1);
        As[0][ca0 + 0][ra0] = a0.x; As[0][ca0 + 1][ra0] = a0.y;
        As[0][ca0 + 2][ra0] = a0.z; As[0][ca0 + 3][ra0] = a0.w;
        As[0][ca1 + 0][ra1] = a1.x; As[0][ca1 + 1][ra1] = a1.y;
        As[0][ca1 + 2][ra1] = a1.z; As[0][ca1 + 3][ra1] = a1.w;
        *(float4*)(&Bs[0][rb0][cb0]) = b0;
        *(float4*)(&Bs[0][rb1][cb1]) = b1;
    }
    __syncthreads();

    for (int k0 = 0; k0 < K; k0 += 16) {
        const int cur = (k0 >> 4) & 1, nxt = cur ^ 1;
        const bool has_next = (k0 + 16) < K;

        float4 na0, na1, nb0, nb1;
        if (has_next) {
            na0 = *(const float4*)(Arow0 + k0 + 16 + ca0);
            na1 = *(const float4*)(Arow1 + k0 + 16 + ca1);
            nb0 = *(const float4*)(Bp0 + (size_t)(k0 + 16) * N);
            nb1 = *(const float4*)(Bp1 + (size_t)(k0 + 16) * N);
        }

#pragma unroll
        for (int kk = 0; kk < 16; kk++) {
            float a[8], b[8];
            *(float4*)(a)     = *(float4*)(&As[cur][kk][ty * 8]);
            *(float4*)(a + 4) = *(float4*)(&As[cur][kk][ty * 8 + 4]);
            *(float4*)(b)     = *(float4*)(&Bs[cur][kk][tx * 8]);
            *(float4*)(b + 4) = *(float4*)(&Bs[cur][kk][tx * 8 + 4]);
#pragma unroll
            for (int i = 0; i < 8; i++)
#pragma unroll
                for (int j = 0; j < 8; j++)
                    acc[i][j] = fmaf(a[i], b[j], acc[i][j]);
        }

        if (has_next) {
            As[nxt][ca0 + 0][ra0] = na0.x; As[nxt][ca0 + 1][ra0] = na0.y;
            As[nxt][ca0 + 2][ra0] = na0.z; As[nxt][ca0 + 3][ra0] = na0.w;
            As[nxt][ca1 + 0][ra1] = na1.x; As[nxt][ca1 + 1][ra1] = na1.y;
            As[nxt][ca1 + 2][ra1] = na1.z; As[nxt][ca1 + 3][ra1] = na1.w;
            *(float4*)(&Bs[nxt][rb0][cb0]) = nb0;
            *(float4*)(&Bs[nxt][rb1][cb1]) = nb1;
            __syncthreads();
        }
    }

    if (EPI == 0) {
#pragma unroll
        for (int i = 0; i < 8; i++) {
            size_t row = (size_t)(m0 + ty * 8 + i) * N + n0 + tx * 8;
            *(float4*)(O + row)     = make_float4(acc[i][0], acc[i][1], acc[i][2], acc[i][3]);
            *(float4*)(O + row + 4) = make_float4(acc[i][4], acc[i][5], acc[i][6], acc[i][7]);
        }
    } else if (EPI == 2) {
#pragma unroll
        for (int i = 0; i < 8; i++) {
            float v[8];
#pragma unroll
            for (int j = 0; j < 8; j++) v[j] = 1.f / (1.f + expf(-acc[i][j]));
            size_t row = (size_t)(m0 + ty * 8 + i) * N + n0 + tx * 8;
            *(float4*)(O + row)     = make_float4(v[0], v[1], v[2], v[3]);
            *(float4*)(O + row + 4) = make_float4(v[4], v[5], v[6], v[7]);
        }
    } else {
        // silu + scatter to [b, h, n, d]
        int e0 = n0 + tx * 8;
        int h = e0 >> 6, d0 = e0 & 63;
#pragma unroll
        for (int i = 0; i < 8; i++) {
            int m = m0 + ty * 8 + i;
            int bb = m >> 13, nn = m & 8191;
            size_t base = ((size_t)(bb * HEADS + h) * NSEQ + nn) * DHEAD + d0;
            float v[8];
#pragma unroll
            for (int j = 0; j < 8; j++) {
                float x = acc[i][j];
                v[j] = x / (1.f + expf(-x));
            }
            *(float4*)(O + base)     = make_float4(v[0], v[1], v[2], v[3]);
            *(float4*)(O + base + 4) = make_float4(v[4], v[5], v[6], v[7]);
        }
    }
}

// =====================================================================
// Phase A: per-chunk KV outer product
// KVch[c][d][e] = sum_i K[c,i,d]*exp(-s*(C-1-i)) * V[c,i,e]
// grid (NCHUNK, HEADS, BATCH), 256 threads, 4x4 per thread over 64x64.
// =====================================================================
__global__ void __launch_bounds__(256) chunk_kv_kernel()
{
    const int c = blockIdx.x, h = blockIdx.y, b = blockIdx.z;
    const int bh = b * HEADS + h;
    const float s = slope_s(h);
    const float* Kp = g_k + ((size_t)bh * NSEQ + (size_t)c * CHUNK) * DHEAD;
    const float* Vp = g_v + ((size_t)bh * NSEQ + (size_t)c * CHUNK) * DHEAD;

    __shared__ float Ks[64][64];
    __shared__ float Vs[64][64];

    const int tid = threadIdx.x;
    const int et = tid & 15, dt = tid >> 4;   // d0 = dt*4, e0 = et*4

    float acc[4][4];
#pragma unroll
    for (int a = 0; a < 4; a++)
#pragma unroll
        for (int e = 0; e < 4; e++) acc[a][e] = 0.f;

    for (int half = 0; half < 2; half++) {
#pragma unroll
        for (int l = 0; l < 4; l++) {
            int lin = tid + l * 256;              // 0..1023
            int r = lin >> 4, c4 = (lin & 15) << 2;
            int row = half * 64 + r;
            float lam = expf(-s * (float)(CHUNK - 1 - row));
            float4 kv4 = *(const float4*)(Kp + (size_t)row * DHEAD + c4);
            kv4.x *= lam; kv4.y *= lam; kv4.z *= lam; kv4.w *= lam;
            *(float4*)(&Ks[r][c4]) = kv4;
            *(float4*)(&Vs[r][c4]) = *(const float4*)(Vp + (size_t)row * DHEAD + c4);
        }
        __syncthreads();
#pragma unroll 16
        for (int i = 0; i < 64; i++) {
            float kk[4], vv[4];
            *(float4*)kk = *(float4*)(&Ks[i][dt * 4]);
            *(float4*)vv = *(float4*)(&Vs[i][et * 4]);
#pragma unroll
            for (int a = 0; a < 4; a++)
#pragma unroll
                for (int e = 0; e < 4; e++)
                    acc[a][e] = fmaf(kk[a], vv[e], acc[a][e]);
        }
        __syncthreads();
    }

    float* out = g_kvch + ((size_t)bh * NCHUNK + c) * (DHEAD * DHEAD);
#pragma unroll
    for (int a = 0; a < 4; a++)
        *(float4*)(out + (size_t)(dt * 4 + a) * DHEAD + et * 4) =
            make_float4(acc[a][0], acc[a][1], acc[a][2], acc[a][3]);
}

// =====================================================================
// Phase B: exclusive prefix scan over chunks of the 64x64 KV state.
// grid 32 (b*h), 256 threads, each owns 16 state elements.
// =====================================================================
__global__ void __launch_bounds__(256) scan_kv_kernel()
{
    const int bh = blockIdx.x;
    const int h = bh & (HEADS - 1);
    const float s = slope_s(h);
    const float lamc = expf(-s * (float)CHUNK);
    const int tid = threadIdx.x;

    float st[16];
#pragma unroll
    for (int j = 0; j < 16; j++) st[j] = 0.f;

    for (int c = 0; c < NCHUNK; c++) {
        size_t base = ((size_t)bh * NCHUNK + c) * (DHEAD * DHEAD);
#pragma unroll
        for (int j = 0; j < 16; j++) {
            g_kvpre[base + j * 256 + tid] = st[j];
            st[j] = fmaf(lamc, st[j], g_kvch[base + j * 256 + tid]);
        }
    }
}

// =====================================================================
// Phase C: per-chunk output.
// O[i,e] = sum_{j<=i} exp(-s(i-j)) (Q_i.K_j) V[j,e]
//        + exp(-s(i+1)) * sum_d Q[i,d] * KVpre[d,e]
// Dynamic smem: Qt(32K) | KU union Kt/Vs(32K) | Ss[j][i](64K) | KVp(16K) | dec
// =====================================================================
#define CO_SMEM_FLOATS 36996
__global__ void __launch_bounds__(256) chunk_out_kernel()
{
    extern __shared__ float sm[];
    float* Qt  = sm;            // [64][128] transposed Q
    float* KU  = sm + 8192;     // stage1: Kt [64][128]; stage2: Vs [128][64]
    float* Ss  = sm + 16384;    // [128][128], stored [j][i]
    float* KVp = sm + 32768;    // [64*64]
    float* dec = sm + 36864;    // [132]

    const int c = blockIdx.x, h = blockIdx.y, b = blockIdx.z;
    const int bh = b * HEADS + h;
    const float s = slope_s(h);
    const int tid = threadIdx.x;

    const float* Qp = g_q + ((size_t)bh * NSEQ + (size_t)c * CHUNK) * DHEAD;
    const float* Kp = g_k + ((size_t)bh * NSEQ + (size_t)c * CHUNK) * DHEAD;
    const float* Vp = g_v + ((size_t)bh * NSEQ + (size_t)c * CHUNK) * DHEAD;
    const float* KVg = g_kvpre + ((size_t)bh * NCHUNK + c) * (DHEAD * DHEAD);

    if (tid < 132) dec[tid] = expf(-s * (float)tid);

#pragma unroll
    for (int l = 0; l < 8; l++) {
        int lin = tid + l * 256;                 // 0..2047
        int r = lin >> 4, c4 = (lin & 15) << 2;
        float4 qv = *(const float4*)(Qp + (size_t)r * DHEAD + c4);
        Qt[(c4 + 0) * 128 + r] = qv.x; Qt[(c4 + 1) * 128 + r] = qv.y;
        Qt[(c4 + 2) * 128 + r] = qv.z; Qt[(c4 + 3) * 128 + r] = qv.w;
        float4 kv = *(const float4*)(Kp + (size_t)r * DHEAD + c4);
        KU[(c4 + 0) * 128 + r] = kv.x; KU[(c4 + 1) * 128 + r] = kv.y;
        KU[(c4 + 2) * 128 + r] = kv.z; KU[(c4 + 3) * 128 + r] = kv.w;
    }
#pragma unroll
    for (int l = 0; l < 16; l++) KVp[tid + l * 256] = KVg[tid + l * 256];
    __syncthreads();

    // ---- stage 1: S = mask(Q K^T), stored transposed Ss[j][i] ----
    {
        const int tx = tid & 15, ty = tid >> 4;
        const int i0 = ty * 8, j0 = tx * 8;
        float acc[8][8];
#pragma unroll
        for (int i = 0; i < 8; i++)
#pragma unroll
            for (int j = 0; j < 8; j++) acc[i][j] = 0.f;

#pragma unroll 8
        for (int d = 0; d < 64; d++) {
            float qa[8], kb[8];
            *(float4*)(qa)     = *(float4*)(&Qt[d * 128 + i0]);
            *(float4*)(qa + 4) = *(float4*)(&Qt[d * 128 + i0 + 4]);
            *(float4*)(kb)     = *(float4*)(&KU[d * 128 + j0]);
            *(float4*)(kb + 4) = *(float4*)(&KU[d * 128 + j0 + 4]);
#pragma unroll
            for (int ii = 0; ii < 8; ii++)
#pragma unroll
                for (int jj = 0; jj < 8; jj++)
                    acc[ii][jj] = fmaf(qa[ii], kb[jj], acc[ii][jj]);
        }
        __syncthreads();   // everyone done reading KU (Kt)

#pragma unroll
        for (int jj = 0; jj < 8; jj++) {
            int j = j0 + jj;
            float v[8];
#pragma unroll
            for (int ii = 0; ii < 8; ii++) {
                int dlt = (i0 + ii) - j;
                v[ii] = (dlt >= 0) ? acc[ii][jj] * dec[dlt] : 0.f;
            }
            *(float4*)(&Ss[j * 128 + i0])     = make_float4(v[0], v[1], v[2], v[3]);
            *(float4*)(&Ss[j * 128 + i0 + 4]) = make_float4(v[4], v[5], v[6], v[7]);
        }
        // load V into KU (row-major [128][64])
#pragma unroll
        for (int l = 0; l < 8; l++) {
            int lin = tid + l * 256;
            int r = lin >> 4, c4 = (lin & 15) << 2;
            *(float4*)(&KU[r * 64 + c4]) =
                *(const float4*)(Vp + (size_t)r * DHEAD + c4);
        }
        __syncthreads();
    }

    // ---- stage 2: O = S @ V + lamq * (Q @ KVpre) ----
    {
        const int i0 = (tid >> 4) * 8;
        const int e0 = (tid & 15) * 4;
        float acc[8][4], ac2[8][4];
#pragma unroll
        for (int i = 0; i < 8; i++)
#pragma unroll
            for (int e = 0; e < 4; e++) { acc[i][e] = 0.f; ac2[i][e] = 0.f; }

#pragma unroll 8
        for (int j = 0; j < 128; j++) {
            float sv[8], vv[4];
            *(float4*)(sv)     = *(float4*)(&Ss[j * 128 + i0]);
            *(float4*)(sv + 4) = *(float4*)(&Ss[j * 128 + i0 + 4]);
            *(float4*)(vv)     = *(float4*)(&KU[j * 64 + e0]);
#pragma unroll
            for (int ii = 0; ii < 8; ii++)
#pragma unroll
                for (int ee = 0; ee < 4; ee++)
                    acc[ii][ee] = fmaf(sv[ii], vv[ee], acc[ii][ee]);
        }
#pragma unroll 8
        for (int d = 0; d < 64; d++) {
            float qa[8], kv[4];
            *(float4*)(qa)     = *(float4*)(&Qt[d * 128 + i0]);
            *(float4*)(qa + 4) = *(float4*)(&Qt[d * 128 + i0 + 4]);
            *(float4*)(kv)     = *(float4*)(&KVp[d * 64 + e0]);
#pragma unroll
            for (int ii = 0; ii < 8; ii++)
#pragma unroll
                for (int ee = 0; ee < 4; ee++)
                    ac2[ii][ee] = fmaf(qa[ii], kv[ee], ac2[ii][ee]);
        }
#pragma unroll
        for (int ii = 0; ii < 8; ii++) {
            int i = i0 + ii;
            float lq = dec[i + 1];
            int m = b * NSEQ + c * CHUNK + i;
            size_t off = (size_t)m * EMB + h * DHEAD + e0;
            float4 r4;
            r4.x = fmaf(lq, ac2[ii][0], acc[ii][0]);
            r4.y = fmaf(lq, ac2[ii][1], acc[ii][1]);
            r4.z = fmaf(lq, ac2[ii][2], acc[ii][2]);
            r4.w = fmaf(lq, ac2[ii][3], acc[ii][3]);
            *(float4*)(g_o + off) = r4;
        }
    }
}

// =====================================================================
// g1 = x @ Wg1  ([16384,1024] @ [1024,64])
// 128 rows x 64 cols per block, 256 threads, 8x4 per thread.
// =====================================================================
__global__ void __launch_bounds__(256) gemm_g1_kernel(
    const float* __restrict__ A, const float* __restrict__ W)
{
    __shared__ float At[16][128];
    __shared__ float Ws[16][64];
    const int tid = threadIdx.x;
    const int tx = tid & 15, ty = tid >> 4;
    const int m0 = blockIdx.x * 128;

    float acc[8][4];
#pragma unroll
    for (int i = 0; i < 8; i++)
#pragma unroll
        for (int j = 0; j < 4; j++) acc[i][j] = 0.f;

    for (int k0 = 0; k0 < EMB; k0 += 16) {
#pragma unroll
        for (int l = 0; l < 2; l++) {
            int lin = tid + l * 256;
            int r = lin >> 2, c = (lin & 3) << 2;
            float4 av = *(const float4*)(A + (size_t)(m0 + r) * EMB + k0 + c);
            At[c + 0][r] = av.x; At[c + 1][r] = av.y;
            At[c + 2][r] = av.z; At[c + 3][r] = av.w;
        }
        {
            int r = tid >> 4, c4 = (tid & 15) << 2;
            *(float4*)(&Ws[r][c4]) = *(const float4*)(W + (size_t)(k0 + r) * DHEAD + c4);
        }
        __syncthreads();
#pragma unroll
        for (int kk = 0; kk < 16; kk++) {
            float a[8], w[4];
            *(float4*)(a)     = *(float4*)(&At[kk][ty * 8]);
            *(float4*)(a + 4) = *(float4*)(&At[kk][ty * 8 + 4]);
            *(float4*)(w)     = *(float4*)(&Ws[kk][tx * 4]);
#pragma unroll
            for (int i = 0; i < 8; i++)
#pragma unroll
                for (int j = 0; j < 4; j++)
                    acc[i][j] = fmaf(a[i], w[j], acc[i][j]);
        }
        __syncthreads();
    }
#pragma unroll
    for (int i = 0; i < 8; i++)
        *(float4*)(g_g1 + (size_t)(m0 + ty * 8 + i) * DHEAD + tx * 4) =
            make_float4(acc[i][0], acc[i][1], acc[i][2], acc[i][3]);
}

// =====================================================================
// LayerNorm(o) * gate -> t.  One block per row, 256 threads, float4 each.
// =====================================================================
__global__ void __launch_bounds__(256) ln_gate_kernel(
    const float* __restrict__ gamma, const float* __restrict__ beta)
{
    const int r = blockIdx.x;
    const int tid = threadIdx.x;
    const float4 v = *(const float4*)(g_o + (size_t)r * EMB + tid * 4);
    float sum = v.x + v.y + v.z + v.w;
    float sq  = v.x * v.x + v.y * v.y + v.z * v.z + v.w * v.w;
#pragma unroll
    for (int o = 16; o > 0; o >>= 1) {
        sum += __shfl_xor_sync(0xFFFFFFFFu, sum, o);
        sq  += __shfl_xor_sync(0xFFFFFFFFu, sq, o);
    }
    __shared__ float rs_[8], rq_[8];
    __shared__ float mu_s, rstd_s;
    int w = tid >> 5;
    if ((tid & 31) == 0) { rs_[w] = sum; rq_[w] = sq; }
    __syncthreads();
    if (tid == 0) {
        float S = 0.f, Q = 0.f;
#pragma unroll
        for (int i = 0; i < 8; i++) { S += rs_[i]; Q += rq_[i]; }
        float mu = S * (1.f / EMB);
        float var = Q * (1.f / EMB) - mu * mu;
        mu_s = mu;
        rstd_s = rsqrtf(var + 1e-5f);
    }
    __syncthreads();
    const float mu = mu_s, rstd = rstd_s;
    const float4 g  = *(const float4*)(gamma + tid * 4);
    const float4 be = *(const float4*)(beta + tid * 4);
    const float4 gt = *(const float4*)(g_gate + (size_t)r * EMB + tid * 4);
    float4 o4;
    o4.x = ((v.x - mu) * rstd * g.x + be.x) * gt.x;
    o4.y = ((v.y - mu) * rstd * g.y + be.y) * gt.y;
    o4.z = ((v.z - mu) * rstd * g.z + be.z) * gt.z;
    o4.w = ((v.w - mu) * rstd * g.w + be.w) * gt.w;
    *(float4*)(g_t + (size_t)r * EMB + tid * 4) = o4;
}

// =====================================================================
extern "C" void kernel_launch(void* const* d_in, const int* in_sizes, int n_in,
                              void* d_out, int out_size)
{
    const float* x     = (const float*)d_in[0];
    const float* Wq    = (const float*)d_in[1];
    const float* Wk    = (const float*)d_in[2];
    const float* Wv    = (const float*)d_in[3];
    const float* Wo    = (const float*)d_in[4];
    const float* gamma = (const float*)d_in[5];
    const float* beta  = (const float*)d_in[6];
    const float* Wg1   = (const float*)d_in[7];
    const float* Wg2   = (const float*)d_in[8];
    float* out = (float*)d_out;

    float *q, *k, *v, *g1p, *gatep, *tp;
    cudaGetSymbolAddress((void**)&q,     g_q);
    cudaGetSymbolAddress((void**)&k,     g_k);
    cudaGetSymbolAddress((void**)&v,     g_v);
    cudaGetSymbolAddress((void**)&g1p,   g_g1);
    cudaGetSymbolAddress((void**)&gatep, g_gate);
    cudaGetSymbolAddress((void**)&tp,    g_t);

    cudaFuncSetAttribute(chunk_out_kernel,
                         cudaFuncAttributeMaxDynamicSharedMemorySize,
                         CO_SMEM_FLOATS * 4);

    // 1. q/k/v = silu(x @ W{q,k,v}) scattered to [b,h,n,d]
    sgemm_kernel<1><<<dim3(EMB / 128, MROWS / 128, 3), 256>>>(
        x, Wq, Wk, Wv, q, k, v, MROWS, EMB, EMB);

    // 2. attention phases
    chunk_kv_kernel<<<dim3(NCHUNK, HEADS, BATCH), 256>>>();
    scan_kv_kernel<<<BATCH * HEADS, 256>>>();
    chunk_out_kernel<<<dim3(NCHUNK, HEADS, BATCH), 256, CO_SMEM_FLOATS * 4>>>();

    // 3. gate path
    gemm_g1_kernel<<<MROWS / 128, 256>>>(x, Wg1);
    sgemm_kernel<2><<<dim3(EMB / 128, MROWS / 128, 1), 256>>>(
        g1p, Wg2, nullptr, nullptr, gatep, nullptr, nullptr, MROWS, EMB, DHEAD);

    // 4. layernorm * gate
    ln_gate_kernel<<<MROWS, 256>>>(gamma, beta);

    // 5. out = t @ Wo
    sgemm_kernel<0><<<dim3(EMB / 128, MROWS / 128, 1), 256>>>(
        tp, Wo, nullptr, nullptr, out, nullptr, nullptr, MROWS, EMB, EMB);
}

// round 7
// speedup vs baseline: 1.9696x; 1.9696x over previous
#include <cuda_runtime.h>
#include <cuda_bf16.h>
#include <cstdint>

// Problem constants
#define HEADS   16
#define DHEAD   64
#define NSEQ    8192
#define EMB     1024
#define BATCH   2
#define CHUNK   128
#define NCHUNK  (NSEQ / CHUNK)          // 64
#define MROWS   (BATCH * NSEQ)          // 16384
#define KEXT    3072                    // 3 * EMB (3xBF16 split)

// ---------------- scratch (device globals: allocation-free) ----------------
__device__ float g_q   [(size_t)BATCH * HEADS * NSEQ * DHEAD];
__device__ float g_k   [(size_t)BATCH * HEADS * NSEQ * DHEAD];
__device__ float g_v   [(size_t)BATCH * HEADS * NSEQ * DHEAD];
__device__ float g_kvch[(size_t)BATCH * HEADS * NCHUNK * DHEAD * DHEAD];
__device__ float g_kvpre[(size_t)BATCH * HEADS * NCHUNK * DHEAD * DHEAD];
__device__ float g_o   [(size_t)MROWS * EMB];
__device__ float g_g1  [(size_t)MROWS * DHEAD];
__device__ float g_gate[(size_t)MROWS * EMB];
__device__ __nv_bfloat16 g_xe[(size_t)MROWS * 2048];            // x: [hi|lo]
__device__ __nv_bfloat16 g_te[(size_t)MROWS * 2048];            // t: [hi|lo]
__device__ __nv_bfloat16 g_we[(size_t)4 * EMB * KEXT];          // Wq,Wk,Wv,Wo: [n][hi|lo|hi]

__device__ __forceinline__ float slope_s(int h) {
    return exp2f(-0.5f * (float)(h + 1)) * (1.0f + 1e-5f);
}

__device__ __forceinline__ uint32_t smem_u32(const void* p) {
    uint32_t a;
    asm("{ .reg .u64 t; cvta.to.shared.u64 t, %1; cvt.u32.u64 %0, t; }"
        : "=r"(a) : "l"(p));
    return a;
}

__device__ __forceinline__ void ldsm4(uint32_t addr, uint32_t* r) {
    asm volatile("ldmatrix.sync.aligned.m8n8.x4.shared.b16 {%0,%1,%2,%3}, [%4];"
                 : "=r"(r[0]), "=r"(r[1]), "=r"(r[2]), "=r"(r[3]) : "r"(addr));
}

__device__ __forceinline__ void mma16816(float* d, const uint32_t* a, const uint32_t* b) {
    asm volatile("mma.sync.aligned.m16n8k16.row.col.f32.bf16.bf16.f32 "
        "{%0,%1,%2,%3}, {%4,%5,%6,%7}, {%8,%9}, {%0,%1,%2,%3};"
        : "+f"(d[0]), "+f"(d[1]), "+f"(d[2]), "+f"(d[3])
        : "r"(a[0]), "r"(a[1]), "r"(a[2]), "r"(a[3]), "r"(b[0]), "r"(b[1]));
}

__device__ __forceinline__ void split_bf16(float v, __nv_bfloat16& h, __nv_bfloat16& l) {
    h = __float2bfloat16(v);
    l = __float2bfloat16(v - __bfloat162float(h));
}

// =====================================================================
// conv_x: x fp32 [M,1024] -> g_xe bf16 [M, 2048] = [hi | lo]
// =====================================================================
__global__ void __launch_bounds__(256) conv_x_kernel(const float* __restrict__ x)
{
    int idx = blockIdx.x * 256 + threadIdx.x;
    int m = idx >> 8;
    int c = (idx & 255) * 4;
    float4 v = *(const float4*)(x + (size_t)m * EMB + c);
    __nv_bfloat16 h[4], l[4];
    split_bf16(v.x, h[0], l[0]); split_bf16(v.y, h[1], l[1]);
    split_bf16(v.z, h[2], l[2]); split_bf16(v.w, h[3], l[3]);
    *(uint2*)(g_xe + (size_t)m * 2048 + c)        = *(uint2*)h;
    *(uint2*)(g_xe + (size_t)m * 2048 + 1024 + c) = *(uint2*)l;
}

// =====================================================================
// conv_w: W [1024,1024] (k rows) -> g_we[z] [n][3072] = [hi | lo | hi]
// =====================================================================
__global__ void __launch_bounds__(256) conv_w_kernel(
    const float* __restrict__ W0, const float* __restrict__ W1,
    const float* __restrict__ W2, const float* __restrict__ W3)
{
    __shared__ float s[32][33];
    const int z = blockIdx.z;
    const float* W = (z == 0) ? W0 : (z == 1) ? W1 : (z == 2) ? W2 : W3;
    const int k0 = blockIdx.y * 32, n0 = blockIdx.x * 32;
    const int tid = threadIdx.x;
#pragma unroll
    for (int l = 0; l < 4; l++) {
        int lin = tid + l * 256;
        int kk = lin >> 5, nn = lin & 31;
        s[kk][nn] = W[(size_t)(k0 + kk) * EMB + n0 + nn];
    }
    __syncthreads();
    __nv_bfloat16* base = g_we + (size_t)z * EMB * KEXT;
#pragma unroll
    for (int l = 0; l < 4; l++) {
        int lin = tid + l * 256;
        int nn = lin >> 5, kk = lin & 31;
        float v = s[kk][nn];
        __nv_bfloat16 h, lo;
        split_bf16(v, h, lo);
        size_t o = (size_t)(n0 + nn) * KEXT + k0 + kk;
        base[o] = h; base[o + 1024] = lo; base[o + 2048] = h;
    }
}

// =====================================================================
// HMMA tensor-core GEMM via mma.sync m16n8k16 bf16 (3xBF16 split).
// CTA tile 128x128, 8 warps (4m x 2n), warp tile 32x64.
// BK = 64 bf16 per chunk, 48 chunks (K_ext = 3072), double-buffered smem.
// smem swizzle: 16B chunk index XOR (row & 7)  (conflict-free STS + LDSM).
// EPI: 0 = plain fp32 store (row stride 1024), 1 = silu + scatter [b,h,n,d].
// =====================================================================
#define HG_SMEM 65536
template<int EPI>
__global__ void __launch_bounds__(256) hgemm_kernel(
    const __nv_bfloat16* __restrict__ Aext,   // [M, 2048] = [hi|lo]
    const __nv_bfloat16* __restrict__ Bext,   // [1024, 3072] per z
    float* __restrict__ O0, float* __restrict__ O1, float* __restrict__ O2)
{
    extern __shared__ char smem[];
    const uint32_t sbase = smem_u32(smem);
    const int tid = threadIdx.x, wid = tid >> 5, lane = tid & 31;
    const int m0 = blockIdx.y * 128, n0 = blockIdx.x * 128;
    const int z = blockIdx.z;
    const __nv_bfloat16* Bq = Bext + (size_t)z * EMB * KEXT;
    float* Oq = O0;
    if (EPI == 1) { if (z == 1) Oq = O1; else if (z == 2) Oq = O2; }

    const int warp_m = wid & 3;      // 32-row slab
    const int warp_n = wid >> 2;     // 64-col slab

    float acc[2][8][4];
#pragma unroll
    for (int mi = 0; mi < 2; mi++)
#pragma unroll
        for (int ni = 0; ni < 8; ni++)
#pragma unroll
            for (int r = 0; r < 4; r++) acc[mi][ni][r] = 0.f;

    // loader lanes: idx -> row (idx>>3), 16B chunk (idx&7)
    const int lr = tid >> 3, lc = tid & 7;
    const char* Ab8 = (const char*)Aext;
    const char* Bb8 = (const char*)Bq;

    // ---- preload chunk 0 into buffer 0 ----
    {
        const char* Ag = Ab8 + (size_t)m0 * 4096;          // acol=0
        const char* Bg = Bb8 + (size_t)n0 * 6144;          // bcol=0
#pragma unroll
        for (int l = 0; l < 4; l++) {
            int r = lr + l * 32;
            uint4 va = *(const uint4*)(Ag + (size_t)r * 4096 + lc * 16);
            uint4 vb = *(const uint4*)(Bg + (size_t)r * 6144 + lc * 16);
            *(uint4*)(smem + ((r * 8 + (lc ^ (r & 7))) << 4)) = va;
            *(uint4*)(smem + 32768 + ((r * 8 + (lc ^ (r & 7))) << 4)) = vb;
        }
    }
    __syncthreads();

    for (int c = 0; c < 48; c++) {
        const int buf = c & 1;
        uint4 pa[4], pb[4];
        if (c < 47) {
            const int cc = c + 1;
            const int acol = (((cc >> 4) == 2) ? 1024 : 0) + (cc & 15) * 64;
            const int bcol = cc * 64;
            const char* Ag = Ab8 + (size_t)m0 * 4096 + acol * 2;
            const char* Bg = Bb8 + (size_t)n0 * 6144 + bcol * 2;
#pragma unroll
            for (int l = 0; l < 4; l++) {
                int r = lr + l * 32;
                pa[l] = *(const uint4*)(Ag + (size_t)r * 4096 + lc * 16);
                pb[l] = *(const uint4*)(Bg + (size_t)r * 6144 + lc * 16);
            }
        }

        const uint32_t Abuf = sbase + buf * 16384;
        const uint32_t Bbuf = sbase + 32768 + buf * 16384;
#pragma unroll
        for (int ks = 0; ks < 4; ks++) {
            uint32_t af[2][4], bf[8][2];
#pragma unroll
            for (int mi = 0; mi < 2; mi++) {
                int row = warp_m * 32 + mi * 16 + (lane & 15);
                int c16 = 2 * ks + (lane >> 4);
                ldsm4(Abuf + ((row * 8 + (c16 ^ (row & 7))) << 4), af[mi]);
            }
#pragma unroll
            for (int nt = 0; nt < 4; nt++) {
                int row = warp_n * 64 + nt * 16 + (lane & 7) + ((lane >> 4) & 1) * 8;
                int c16 = 2 * ks + ((lane >> 3) & 1);
                uint32_t t[4];
                ldsm4(Bbuf + ((row * 8 + (c16 ^ (row & 7))) << 4), t);
                bf[nt * 2][0] = t[0]; bf[nt * 2][1] = t[1];
                bf[nt * 2 + 1][0] = t[2]; bf[nt * 2 + 1][1] = t[3];
            }
#pragma unroll
            for (int mi = 0; mi < 2; mi++)
#pragma unroll
                for (int ni = 0; ni < 8; ni++)
                    mma16816(acc[mi][ni], af[mi], bf[ni]);
        }

        if (c < 47) {
            const int nbuf = buf ^ 1;
            char* As = smem + nbuf * 16384;
            char* Bs = smem + 32768 + nbuf * 16384;
#pragma unroll
            for (int l = 0; l < 4; l++) {
                int r = lr + l * 32;
                *(uint4*)(As + ((r * 8 + (lc ^ (r & 7))) << 4)) = pa[l];
                *(uint4*)(Bs + ((r * 8 + (lc ^ (r & 7))) << 4)) = pb[l];
            }
        }
        __syncthreads();
    }

    // ---- epilogue ----
    const int em0 = m0 + warp_m * 32;
    const int en0 = n0 + warp_n * 64;
    const int er = lane >> 2, ec = (lane & 3) * 2;
#pragma unroll
    for (int mi = 0; mi < 2; mi++) {
#pragma unroll
        for (int h2 = 0; h2 < 2; h2++) {
            const int m = em0 + mi * 16 + er + h2 * 8;
            if (EPI == 0) {
                float* row = Oq + (size_t)m * EMB + en0 + ec;
#pragma unroll
                for (int ni = 0; ni < 8; ni++) {
                    float2 v2 = make_float2(acc[mi][ni][h2 * 2], acc[mi][ni][h2 * 2 + 1]);
                    *(float2*)(row + ni * 8) = v2;
                }
            } else {
                const int bb = m >> 13, nn = m & 8191;
                const int h = en0 >> 6;                 // 64-wide slab: single head
                float* base = Oq + ((size_t)(bb * HEADS + h) * NSEQ + nn) * DHEAD;
                const int d0 = (en0 & 63) + ec;
#pragma unroll
                for (int ni = 0; ni < 8; ni++) {
                    float a0 = acc[mi][ni][h2 * 2], a1 = acc[mi][ni][h2 * 2 + 1];
                    float2 v2;
                    v2.x = a0 / (1.f + expf(-a0));
                    v2.y = a1 / (1.f + expf(-a1));
                    *(float2*)(base + d0 + ni * 8) = v2;
                }
            }
        }
    }
}

// =====================================================================
// FFMA SGEMM (gate path N=1024 K=64, EPI 2 = sigmoid store)
// =====================================================================
template<int EPI>
__global__ void __launch_bounds__(256) sgemm_kernel(
    const float* __restrict__ A,
    const float* __restrict__ B0,
    float* __restrict__ O0,
    int M, int N, int K)
{
    const float* B = B0;
    float* O = O0;

    __shared__ float As[2][16][128];
    __shared__ float Bs[2][16][128];

    const int tid = threadIdx.x;
    const int tx = tid & 15, ty = tid >> 4;
    const int m0 = blockIdx.y * 128, n0 = blockIdx.x * 128;

    const int lin1 = tid + 256;
    const int ra0 = tid  >> 2, ca0 = (tid  & 3) << 2;
    const int ra1 = lin1 >> 2, ca1 = (lin1 & 3) << 2;
    const int rb0 = tid  >> 5, cb0 = (tid  & 31) << 2;
    const int rb1 = lin1 >> 5, cb1 = (lin1 & 31) << 2;

    const float* Arow0 = A + (size_t)(m0 + ra0) * K;
    const float* Arow1 = A + (size_t)(m0 + ra1) * K;
    const float* Bp0   = B + (size_t)rb0 * N + n0 + cb0;
    const float* Bp1   = B + (size_t)rb1 * N + n0 + cb1;

    float acc[8][8];
#pragma unroll
    for (int i = 0; i < 8; i++)
#pragma unroll
        for (int j = 0; j < 8; j++) acc[i][j] = 0.f;

    {
        float4 a0 = *(const float4*)(Arow0 + ca0);
        float4 a1 = *(const float4*)(Arow1 + ca1);
        float4 b0 = *(const float4*)(Bp0);
        float4 b1 = *(const float4*)(Bp1);
        As[0][ca0 + 0][ra0] = a0.x; As[0][ca0 + 1][ra0] = a0.y;
        As[0][ca0 + 2][ra0] = a0.z; As[0][ca0 + 3][ra0] = a0.w;
        As[0][ca1 + 0][ra1] = a1.x; As[0][ca1 + 1][ra1] = a1.y;
        As[0][ca1 + 2][ra1] = a1.z; As[0][ca1 + 3][ra1] = a1.w;
        *(float4*)(&Bs[0][rb0][cb0]) = b0;
        *(float4*)(&Bs[0][rb1][cb1]) = b1;
    }
    __syncthreads();

    for (int k0 = 0; k0 < K; k0 += 16) {
        const int cur = (k0 >> 4) & 1, nxt = cur ^ 1;
        const bool has_next = (k0 + 16) < K;

        float4 na0, na1, nb0, nb1;
        if (has_next) {
            na0 = *(const float4*)(Arow0 + k0 + 16 + ca0);
            na1 = *(const float4*)(Arow1 + k0 + 16 + ca1);
            nb0 = *(const float4*)(Bp0 + (size_t)(k0 + 16) * N);
            nb1 = *(const float4*)(Bp1 + (size_t)(k0 + 16) * N);
        }

#pragma unroll
        for (int kk = 0; kk < 16; kk++) {
            float a[8], b[8];
            *(float4*)(a)     = *(float4*)(&As[cur][kk][ty * 8]);
            *(float4*)(a + 4) = *(float4*)(&As[cur][kk][ty * 8 + 4]);
            *(float4*)(b)     = *(float4*)(&Bs[cur][kk][tx * 8]);
            *(float4*)(b + 4) = *(float4*)(&Bs[cur][kk][tx * 8 + 4]);
#pragma unroll
            for (int i = 0; i < 8; i++)
#pragma unroll
                for (int j = 0; j < 8; j++)
                    acc[i][j] = fmaf(a[i], b[j], acc[i][j]);
        }

        if (has_next) {
            As[nxt][ca0 + 0][ra0] = na0.x; As[nxt][ca0 + 1][ra0] = na0.y;
            As[nxt][ca0 + 2][ra0] = na0.z; As[nxt][ca0 + 3][ra0] = na0.w;
            As[nxt][ca1 + 0][ra1] = na1.x; As[nxt][ca1 + 1][ra1] = na1.y;
            As[nxt][ca1 + 2][ra1] = na1.z; As[nxt][ca1 + 3][ra1] = na1.w;
            *(float4*)(&Bs[nxt][rb0][cb0]) = nb0;
            *(float4*)(&Bs[nxt][rb1][cb1]) = nb1;
            __syncthreads();
        }
    }

    if (EPI == 2) {
#pragma unroll
        for (int i = 0; i < 8; i++) {
            float v[8];
#pragma unroll
            for (int j = 0; j < 8; j++) v[j] = 1.f / (1.f + expf(-acc[i][j]));
            size_t row = (size_t)(m0 + ty * 8 + i) * N + n0 + tx * 8;
            *(float4*)(O + row)     = make_float4(v[0], v[1], v[2], v[3]);
            *(float4*)(O + row + 4) = make_float4(v[4], v[5], v[6], v[7]);
        }
    } else {
#pragma unroll
        for (int i = 0; i < 8; i++) {
            size_t row = (size_t)(m0 + ty * 8 + i) * N + n0 + tx * 8;
            *(float4*)(O + row)     = make_float4(acc[i][0], acc[i][1], acc[i][2], acc[i][3]);
            *(float4*)(O + row + 4) = make_float4(acc[i][4], acc[i][5], acc[i][6], acc[i][7]);
        }
    }
}

// =====================================================================
// Phase A: per-chunk KV outer product
// =====================================================================
__global__ void __launch_bounds__(256) chunk_kv_kernel()
{
    const int c = blockIdx.x, h = blockIdx.y, b = blockIdx.z;
    const int bh = b * HEADS + h;
    const float s = slope_s(h);
    const float* Kp = g_k + ((size_t)bh * NSEQ + (size_t)c * CHUNK) * DHEAD;
    const float* Vp = g_v + ((size_t)bh * NSEQ + (size_t)c * CHUNK) * DHEAD;

    __shared__ float Ks[64][64];
    __shared__ float Vs[64][64];

    const int tid = threadIdx.x;
    const int et = tid & 15, dt = tid >> 4;

    float acc[4][4];
#pragma unroll
    for (int a = 0; a < 4; a++)
#pragma unroll
        for (int e = 0; e < 4; e++) acc[a][e] = 0.f;

    for (int half = 0; half < 2; half++) {
#pragma unroll
        for (int l = 0; l < 4; l++) {
            int lin = tid + l * 256;
            int r = lin >> 4, c4 = (lin & 15) << 2;
            int row = half * 64 + r;
            float lam = expf(-s * (float)(CHUNK - 1 - row));
            float4 kv4 = *(const float4*)(Kp + (size_t)row * DHEAD + c4);
            kv4.x *= lam; kv4.y *= lam; kv4.z *= lam; kv4.w *= lam;
            *(float4*)(&Ks[r][c4]) = kv4;
            *(float4*)(&Vs[r][c4]) = *(const float4*)(Vp + (size_t)row * DHEAD + c4);
        }
        __syncthreads();
#pragma unroll 16
        for (int i = 0; i < 64; i++) {
            float kk[4], vv[4];
            *(float4*)kk = *(float4*)(&Ks[i][dt * 4]);
            *(float4*)vv = *(float4*)(&Vs[i][et * 4]);
#pragma unroll
            for (int a = 0; a < 4; a++)
#pragma unroll
                for (int e = 0; e < 4; e++)
                    acc[a][e] = fmaf(kk[a], vv[e], acc[a][e]);
        }
        __syncthreads();
    }

    float* out = g_kvch + ((size_t)bh * NCHUNK + c) * (DHEAD * DHEAD);
#pragma unroll
    for (int a = 0; a < 4; a++)
        *(float4*)(out + (size_t)(dt * 4 + a) * DHEAD + et * 4) =
            make_float4(acc[a][0], acc[a][1], acc[a][2], acc[a][3]);
}

// =====================================================================
// Phase B: exclusive prefix scan over chunks of the 64x64 KV state.
// =====================================================================
__global__ void __launch_bounds__(256) scan_kv_kernel()
{
    const int bh = blockIdx.x;
    const int h = bh & (HEADS - 1);
    const float s = slope_s(h);
    const float lamc = expf(-s * (float)CHUNK);
    const int tid = threadIdx.x;

    float st[16];
#pragma unroll
    for (int j = 0; j < 16; j++) st[j] = 0.f;

    for (int c = 0; c < NCHUNK; c++) {
        size_t base = ((size_t)bh * NCHUNK + c) * (DHEAD * DHEAD);
#pragma unroll
        for (int j = 0; j < 16; j++) {
            g_kvpre[base + j * 256 + tid] = st[j];
            st[j] = fmaf(lamc, st[j], g_kvch[base + j * 256 + tid]);
        }
    }
}

// =====================================================================
// Phase C: per-chunk output.
// =====================================================================
#define CO_SMEM_FLOATS 36996
__global__ void __launch_bounds__(256) chunk_out_kernel()
{
    extern __shared__ float sm[];
    float* Qt  = sm;            // [64][128]
    float* KU  = sm + 8192;     // Kt [64][128] / Vs [128][64]
    float* Ss  = sm + 16384;    // [128][128] transposed scores
    float* KVp = sm + 32768;    // [64*64]
    float* dec = sm + 36864;    // [132]

    const int c = blockIdx.x, h = blockIdx.y, b = blockIdx.z;
    const int bh = b * HEADS + h;
    const float s = slope_s(h);
    const int tid = threadIdx.x;

    const float* Qp = g_q + ((size_t)bh * NSEQ + (size_t)c * CHUNK) * DHEAD;
    const float* Kp = g_k + ((size_t)bh * NSEQ + (size_t)c * CHUNK) * DHEAD;
    const float* Vp = g_v + ((size_t)bh * NSEQ + (size_t)c * CHUNK) * DHEAD;
    const float* KVg = g_kvpre + ((size_t)bh * NCHUNK + c) * (DHEAD * DHEAD);

    if (tid < 132) dec[tid] = expf(-s * (float)tid);

#pragma unroll
    for (int l = 0; l < 8; l++) {
        int lin = tid + l * 256;
        int r = lin >> 4, c4 = (lin & 15) << 2;
        float4 qv = *(const float4*)(Qp + (size_t)r * DHEAD + c4);
        Qt[(c4 + 0) * 128 + r] = qv.x; Qt[(c4 + 1) * 128 + r] = qv.y;
        Qt[(c4 + 2) * 128 + r] = qv.z; Qt[(c4 + 3) * 128 + r] = qv.w;
        float4 kv = *(const float4*)(Kp + (size_t)r * DHEAD + c4);
        KU[(c4 + 0) * 128 + r] = kv.x; KU[(c4 + 1) * 128 + r] = kv.y;
        KU[(c4 + 2) * 128 + r] = kv.z; KU[(c4 + 3) * 128 + r] = kv.w;
    }
#pragma unroll
    for (int l = 0; l < 16; l++) KVp[tid + l * 256] = KVg[tid + l * 256];
    __syncthreads();

    {
        const int tx = tid & 15, ty = tid >> 4;
        const int i0 = ty * 8, j0 = tx * 8;
        float acc[8][8];
#pragma unroll
        for (int i = 0; i < 8; i++)
#pragma unroll
            for (int j = 0; j < 8; j++) acc[i][j] = 0.f;

#pragma unroll 8
        for (int d = 0; d < 64; d++) {
            float qa[8], kb[8];
            *(float4*)(qa)     = *(float4*)(&Qt[d * 128 + i0]);
            *(float4*)(qa + 4) = *(float4*)(&Qt[d * 128 + i0 + 4]);
            *(float4*)(kb)     = *(float4*)(&KU[d * 128 + j0]);
            *(float4*)(kb + 4) = *(float4*)(&KU[d * 128 + j0 + 4]);
#pragma unroll
            for (int ii = 0; ii < 8; ii++)
#pragma unroll
                for (int jj = 0; jj < 8; jj++)
                    acc[ii][jj] = fmaf(qa[ii], kb[jj], acc[ii][jj]);
        }
        __syncthreads();

#pragma unroll
        for (int jj = 0; jj < 8; jj++) {
            int j = j0 + jj;
            float v[8];
#pragma unroll
            for (int ii = 0; ii < 8; ii++) {
                int dlt = (i0 + ii) - j;
                v[ii] = (dlt >= 0) ? acc[ii][jj] * dec[dlt] : 0.f;
            }
            *(float4*)(&Ss[j * 128 + i0])     = make_float4(v[0], v[1], v[2], v[3]);
            *(float4*)(&Ss[j * 128 + i0 + 4]) = make_float4(v[4], v[5], v[6], v[7]);
        }
#pragma unroll
        for (int l = 0; l < 8; l++) {
            int lin = tid + l * 256;
            int r = lin >> 4, c4 = (lin & 15) << 2;
            *(float4*)(&KU[r * 64 + c4]) =
                *(const float4*)(Vp + (size_t)r * DHEAD + c4);
        }
        __syncthreads();
    }

    {
        const int i0 = (tid >> 4) * 8;
        const int e0 = (tid & 15) * 4;
        float acc[8][4], ac2[8][4];
#pragma unroll
        for (int i = 0; i < 8; i++)
#pragma unroll
            for (int e = 0; e < 4; e++) { acc[i][e] = 0.f; ac2[i][e] = 0.f; }

#pragma unroll 8
        for (int j = 0; j < 128; j++) {
            float sv[8], vv[4];
            *(float4*)(sv)     = *(float4*)(&Ss[j * 128 + i0]);
            *(float4*)(sv + 4) = *(float4*)(&Ss[j * 128 + i0 + 4]);
            *(float4*)(vv)     = *(float4*)(&KU[j * 64 + e0]);
#pragma unroll
            for (int ii = 0; ii < 8; ii++)
#pragma unroll
                for (int ee = 0; ee < 4; ee++)
                    acc[ii][ee] = fmaf(sv[ii], vv[ee], acc[ii][ee]);
        }
#pragma unroll 8
        for (int d = 0; d < 64; d++) {
            float qa[8], kv[4];
            *(float4*)(qa)     = *(float4*)(&Qt[d * 128 + i0]);
            *(float4*)(qa + 4) = *(float4*)(&Qt[d * 128 + i0 + 4]);
            *(float4*)(kv)     = *(float4*)(&KVp[d * 64 + e0]);
#pragma unroll
            for (int ii = 0; ii < 8; ii++)
#pragma unroll
                for (int ee = 0; ee < 4; ee++)
                    ac2[ii][ee] = fmaf(qa[ii], kv[ee], ac2[ii][ee]);
        }
#pragma unroll
        for (int ii = 0; ii < 8; ii++) {
            int i = i0 + ii;
            float lq = dec[i + 1];
            int m = b * NSEQ + c * CHUNK + i;
            size_t off = (size_t)m * EMB + h * DHEAD + e0;
            float4 r4;
            r4.x = fmaf(lq, ac2[ii][0], acc[ii][0]);
            r4.y = fmaf(lq, ac2[ii][1], acc[ii][1]);
            r4.z = fmaf(lq, ac2[ii][2], acc[ii][2]);
            r4.w = fmaf(lq, ac2[ii][3], acc[ii][3]);
            *(float4*)(g_o + off) = r4;
        }
    }
}

// =====================================================================
// g1 = x @ Wg1  ([16384,1024] @ [1024,64])
// =====================================================================
__global__ void __launch_bounds__(256) gemm_g1_kernel(
    const float* __restrict__ A, const float* __restrict__ W)
{
    __shared__ float At[16][128];
    __shared__ float Ws[16][64];
    const int tid = threadIdx.x;
    const int tx = tid & 15, ty = tid >> 4;
    const int m0 = blockIdx.x * 128;

    float acc[8][4];
#pragma unroll
    for (int i = 0; i < 8; i++)
#pragma unroll
        for (int j = 0; j < 4; j++) acc[i][j] = 0.f;

    for (int k0 = 0; k0 < EMB; k0 += 16) {
#pragma unroll
        for (int l = 0; l < 2; l++) {
            int lin = tid + l * 256;
            int r = lin >> 2, c = (lin & 3) << 2;
            float4 av = *(const float4*)(A + (size_t)(m0 + r) * EMB + k0 + c);
            At[c + 0][r] = av.x; At[c + 1][r] = av.y;
            At[c + 2][r] = av.z; At[c + 3][r] = av.w;
        }
        {
            int r = tid >> 4, c4 = (tid & 15) << 2;
            *(float4*)(&Ws[r][c4]) = *(const float4*)(W + (size_t)(k0 + r) * DHEAD + c4);
        }
        __syncthreads();
#pragma unroll
        for (int kk = 0; kk < 16; kk++) {
            float a[8], w[4];
            *(float4*)(a)     = *(float4*)(&At[kk][ty * 8]);
            *(float4*)(a + 4) = *(float4*)(&At[kk][ty * 8 + 4]);
            *(float4*)(w)     = *(float4*)(&Ws[kk][tx * 4]);
#pragma unroll
            for (int i = 0; i < 8; i++)
#pragma unroll
                for (int j = 0; j < 4; j++)
                    acc[i][j] = fmaf(a[i], w[j], acc[i][j]);
        }
        __syncthreads();
    }
#pragma unroll
    for (int i = 0; i < 8; i++)
        *(float4*)(g_g1 + (size_t)(m0 + ty * 8 + i) * DHEAD + tx * 4) =
            make_float4(acc[i][0], acc[i][1], acc[i][2], acc[i][3]);
}

// =====================================================================
// LayerNorm(o) * gate -> split bf16 hi/lo into g_te (feeds Wo GEMM)
// =====================================================================
__global__ void __launch_bounds__(256) ln_gate_kernel(
    const float* __restrict__ gamma, const float* __restrict__ beta)
{
    const int r = blockIdx.x;
    const int tid = threadIdx.x;
    const float4 v = *(const float4*)(g_o + (size_t)r * EMB + tid * 4);
    float sum = v.x + v.y + v.z + v.w;
    float sq  = v.x * v.x + v.y * v.y + v.z * v.z + v.w * v.w;
#pragma unroll
    for (int o = 16; o > 0; o >>= 1) {
        sum += __shfl_xor_sync(0xFFFFFFFFu, sum, o);
        sq  += __shfl_xor_sync(0xFFFFFFFFu, sq, o);
    }
    __shared__ float rs_[8], rq_[8];
    __shared__ float mu_s, rstd_s;
    int w = tid >> 5;
    if ((tid & 31) == 0) { rs_[w] = sum; rq_[w] = sq; }
    __syncthreads();
    if (tid == 0) {
        float S = 0.f, Q = 0.f;
#pragma unroll
        for (int i = 0; i < 8; i++) { S += rs_[i]; Q += rq_[i]; }
        float mu = S * (1.f / EMB);
        float var = Q * (1.f / EMB) - mu * mu;
        mu_s = mu;
        rstd_s = rsqrtf(var + 1e-5f);
    }
    __syncthreads();
    const float mu = mu_s, rstd = rstd_s;
    const float4 g  = *(const float4*)(gamma + tid * 4);
    const float4 be = *(const float4*)(beta + tid * 4);
    const float4 gt = *(const float4*)(g_gate + (size_t)r * EMB + tid * 4);
    float t0 = ((v.x - mu) * rstd * g.x + be.x) * gt.x;
    float t1 = ((v.y - mu) * rstd * g.y + be.y) * gt.y;
    float t2 = ((v.z - mu) * rstd * g.z + be.z) * gt.z;
    float t3 = ((v.w - mu) * rstd * g.w + be.w) * gt.w;
    __nv_bfloat16 h[4], l[4];
    split_bf16(t0, h[0], l[0]); split_bf16(t1, h[1], l[1]);
    split_bf16(t2, h[2], l[2]); split_bf16(t3, h[3], l[3]);
    *(uint2*)(g_te + (size_t)r * 2048 + tid * 4)        = *(uint2*)h;
    *(uint2*)(g_te + (size_t)r * 2048 + 1024 + tid * 4) = *(uint2*)l;
}

// =====================================================================
extern "C" void kernel_launch(void* const* d_in, const int* in_sizes, int n_in,
                              void* d_out, int out_size)
{
    const float* x     = (const float*)d_in[0];
    const float* Wq    = (const float*)d_in[1];
    const float* Wk    = (const float*)d_in[2];
    const float* Wv    = (const float*)d_in[3];
    const float* Wo    = (const float*)d_in[4];
    const float* gamma = (const float*)d_in[5];
    const float* beta  = (const float*)d_in[6];
    const float* Wg1   = (const float*)d_in[7];
    const float* Wg2   = (const float*)d_in[8];
    float* out = (float*)d_out;

    float *q, *k, *v, *g1p, *gatep;
    __nv_bfloat16 *xep, *tep, *wep;
    cudaGetSymbolAddress((void**)&q,     g_q);
    cudaGetSymbolAddress((void**)&k,     g_k);
    cudaGetSymbolAddress((void**)&v,     g_v);
    cudaGetSymbolAddress((void**)&g1p,   g_g1);
    cudaGetSymbolAddress((void**)&gatep, g_gate);
    cudaGetSymbolAddress((void**)&xep,   g_xe);
    cudaGetSymbolAddress((void**)&tep,   g_te);
    cudaGetSymbolAddress((void**)&wep,   g_we);

    cudaFuncSetAttribute(chunk_out_kernel,
                         cudaFuncAttributeMaxDynamicSharedMemorySize,
                         CO_SMEM_FLOATS * 4);
    cudaFuncSetAttribute(hgemm_kernel<0>,
                         cudaFuncAttributeMaxDynamicSharedMemorySize, HG_SMEM);
    cudaFuncSetAttribute(hgemm_kernel<1>,
                         cudaFuncAttributeMaxDynamicSharedMemorySize, HG_SMEM);

    // 0. split conversions
    conv_x_kernel<<<MROWS, 256>>>(x);
    conv_w_kernel<<<dim3(32, 32, 4), 256>>>(Wq, Wk, Wv, Wo);

    // 1. q/k/v = silu(x @ W{q,k,v}) via HMMA, scattered to [b,h,n,d]
    hgemm_kernel<1><<<dim3(8, 128, 3), 256, HG_SMEM>>>(xep, wep, q, k, v);

    // 2. attention phases
    chunk_kv_kernel<<<dim3(NCHUNK, HEADS, BATCH), 256>>>();
    scan_kv_kernel<<<BATCH * HEADS, 256>>>();
    chunk_out_kernel<<<dim3(NCHUNK, HEADS, BATCH), 256, CO_SMEM_FLOATS * 4>>>();

    // 3. gate path (small, FFMA)
    gemm_g1_kernel<<<MROWS / 128, 256>>>(x, Wg1);
    sgemm_kernel<2><<<dim3(EMB / 128, MROWS / 128, 1), 256>>>(
        g1p, Wg2, gatep, MROWS, EMB, DHEAD);

    // 4. layernorm * gate -> t (hi/lo split)
    ln_gate_kernel<<<MROWS, 256>>>(gamma, beta);

    // 5. out = t @ Wo via HMMA
    hgemm_kernel<0><<<dim3(8, 128, 1), 256, HG_SMEM>>>(
        tep, wep + (size_t)3 * EMB * KEXT, out, nullptr, nullptr);
}

// round 17
// speedup vs baseline: 2.5104x; 1.2746x over previous
#include <cuda_runtime.h>
#include <cuda_bf16.h>
#include <cstdint>

// Problem constants
#define HEADS   16
#define DHEAD   64
#define NSEQ    8192
#define EMB     1024
#define BATCH   2
#define CHUNK   128
#define NCHUNK  (NSEQ / CHUNK)          // 64
#define MROWS   (BATCH * NSEQ)          // 16384
#define KEXT    3072                    // 3 * EMB (3xBF16 split)

// ---------------- scratch (device globals: allocation-free) ----------------
__device__ float g_q   [(size_t)BATCH * HEADS * NSEQ * DHEAD];
__device__ float g_k   [(size_t)BATCH * HEADS * NSEQ * DHEAD];
__device__ float g_v   [(size_t)BATCH * HEADS * NSEQ * DHEAD];
__device__ float g_kvch[(size_t)BATCH * HEADS * NCHUNK * DHEAD * DHEAD];
__device__ float g_kvpre[(size_t)BATCH * HEADS * NCHUNK * DHEAD * DHEAD];
__device__ float g_o   [(size_t)MROWS * EMB];
__device__ float g_g1  [(size_t)MROWS * DHEAD];
__device__ float g_gate[(size_t)MROWS * EMB];
__device__ __nv_bfloat16 g_xe[(size_t)MROWS * 2048];            // x: [hi|lo]
__device__ __nv_bfloat16 g_te[(size_t)MROWS * 2048];            // t: [hi|lo]
__device__ __nv_bfloat16 g_we[(size_t)4 * EMB * KEXT];          // Wq,Wk,Wv,Wo: [n][hi|lo|hi]

__device__ __forceinline__ float slope_s(int h) {
    return exp2f(-0.5f * (float)(h + 1)) * (1.0f + 1e-5f);
}

__device__ __forceinline__ uint32_t smem_u32(const void* p) {
    uint32_t a;
    asm("{ .reg .u64 t; cvta.to.shared.u64 t, %1; cvt.u32.u64 %0, t; }"
        : "=r"(a) : "l"(p));
    return a;
}

__device__ __forceinline__ void ldsm4(uint32_t addr, uint32_t* r) {
    asm volatile("ldmatrix.sync.aligned.m8n8.x4.shared.b16 {%0,%1,%2,%3}, [%4];"
                 : "=r"(r[0]), "=r"(r[1]), "=r"(r[2]), "=r"(r[3]) : "r"(addr));
}

__device__ __forceinline__ void mma16816(float* d, const uint32_t* a, const uint32_t* b) {
    asm volatile("mma.sync.aligned.m16n8k16.row.col.f32.bf16.bf16.f32 "
        "{%0,%1,%2,%3}, {%4,%5,%6,%7}, {%8,%9}, {%0,%1,%2,%3};"
        : "+f"(d[0]), "+f"(d[1]), "+f"(d[2]), "+f"(d[3])
        : "r"(a[0]), "r"(a[1]), "r"(a[2]), "r"(a[3]), "r"(b[0]), "r"(b[1]));
}

#define CP_ASYNC16(dst, src) \
    asm volatile("cp.async.cg.shared.global [%0], [%1], 16;" \
                 :: "r"(dst), "l"(src))
#define CP_COMMIT() asm volatile("cp.async.commit_group;")
#define CP_WAIT0()  asm volatile("cp.async.wait_group 0;" ::: "memory")

__device__ __forceinline__ void split_bf16(float v, __nv_bfloat16& h, __nv_bfloat16& l) {
    h = __float2bfloat16(v);
    l = __float2bfloat16(v - __bfloat162float(h));
}

// =====================================================================
// conv_x: x fp32 [M,1024] -> g_xe bf16 [M, 2048] = [hi | lo]
// =====================================================================
__global__ void __launch_bounds__(256) conv_x_kernel(const float* __restrict__ x)
{
    int idx = blockIdx.x * 256 + threadIdx.x;
    int m = idx >> 8;
    int c = (idx & 255) * 4;
    float4 v = *(const float4*)(x + (size_t)m * EMB + c);
    __nv_bfloat16 h[4], l[4];
    split_bf16(v.x, h[0], l[0]); split_bf16(v.y, h[1], l[1]);
    split_bf16(v.z, h[2], l[2]); split_bf16(v.w, h[3], l[3]);
    *(uint2*)(g_xe + (size_t)m * 2048 + c)        = *(uint2*)h;
    *(uint2*)(g_xe + (size_t)m * 2048 + 1024 + c) = *(uint2*)l;
}

// =====================================================================
// conv_w: W [1024,1024] (k rows) -> g_we[z] [n][3072] = [hi | lo | hi]
// =====================================================================
__global__ void __launch_bounds__(256) conv_w_kernel(
    const float* __restrict__ W0, const float* __restrict__ W1,
    const float* __restrict__ W2, const float* __restrict__ W3)
{
    __shared__ float s[32][33];
    const int z = blockIdx.z;
    const float* W = (z == 0) ? W0 : (z == 1) ? W1 : (z == 2) ? W2 : W3;
    const int k0 = blockIdx.y * 32, n0 = blockIdx.x * 32;
    const int tid = threadIdx.x;
#pragma unroll
    for (int l = 0; l < 4; l++) {
        int lin = tid + l * 256;
        int kk = lin >> 5, nn = lin & 31;
        s[kk][nn] = W[(size_t)(k0 + kk) * EMB + n0 + nn];
    }
    __syncthreads();
    __nv_bfloat16* base = g_we + (size_t)z * EMB * KEXT;
#pragma unroll
    for (int l = 0; l < 4; l++) {
        int lin = tid + l * 256;
        int nn = lin >> 5, kk = lin & 31;
        float v = s[kk][nn];
        __nv_bfloat16 h, lo;
        split_bf16(v, h, lo);
        size_t o = (size_t)(n0 + nn) * KEXT + k0 + kk;
        base[o] = h; base[o + 1024] = lo; base[o + 2048] = h;
    }
}

// =====================================================================
// HMMA tensor-core GEMM via mma.sync m16n8k16 bf16 (3xBF16 split).
// CTA tile 128x128, 8 warps (4m x 2n), warp tile 32x64.
// BK = 64 bf16 per chunk, 48 chunks (K_ext = 3072), double-buffered smem,
// cp.async staging (no register prefetch) -> 2 CTAs/SM.
// smem swizzle: 16B chunk index XOR (row & 7)  (conflict-free STS + LDSM).
// EPI: 0 = plain fp32 store (row stride 1024), 1 = silu + scatter [b,h,n,d].
// =====================================================================
#define HG_SMEM 65536
template<int EPI>
__global__ void __launch_bounds__(256, 2) hgemm_kernel(
    const __nv_bfloat16* __restrict__ Aext,   // [M, 2048] = [hi|lo]
    const __nv_bfloat16* __restrict__ Bext,   // [1024, 3072] per z
    float* __restrict__ O0, float* __restrict__ O1, float* __restrict__ O2)
{
    extern __shared__ char smem[];
    const uint32_t sbase = smem_u32(smem);
    const int tid = threadIdx.x, wid = tid >> 5, lane = tid & 31;
    const int m0 = blockIdx.y * 128, n0 = blockIdx.x * 128;
    const int z = blockIdx.z;
    const __nv_bfloat16* Bq = Bext + (size_t)z * EMB * KEXT;
    float* Oq = O0;
    if (EPI == 1) { if (z == 1) Oq = O1; else if (z == 2) Oq = O2; }

    const int warp_m = wid & 3;      // 32-row slab
    const int warp_n = wid >> 2;     // 64-col slab

    float acc[2][8][4];
#pragma unroll
    for (int mi = 0; mi < 2; mi++)
#pragma unroll
        for (int ni = 0; ni < 8; ni++)
#pragma unroll
            for (int r = 0; r < 4; r++) acc[mi][ni][r] = 0.f;

    // loader lanes: idx -> row (idx>>3), 16B chunk (idx&7)
    const int lr = tid >> 3, lc = tid & 7;
    const char* Ab8 = (const char*)Aext;
    const char* Bb8 = (const char*)Bq;

    // ---- preload chunk 0 into buffer 0 via cp.async ----
    {
        const char* Ag = Ab8 + (size_t)m0 * 4096;          // acol=0
        const char* Bg = Bb8 + (size_t)n0 * 6144;          // bcol=0
#pragma unroll
        for (int l = 0; l < 4; l++) {
            int r = lr + l * 32;
            uint32_t so = (uint32_t)((r * 8 + (lc ^ (r & 7))) << 4);
            CP_ASYNC16(sbase + so,         Ag + (size_t)r * 4096 + lc * 16);
            CP_ASYNC16(sbase + 32768 + so, Bg + (size_t)r * 6144 + lc * 16);
        }
        CP_COMMIT();
        CP_WAIT0();
    }
    __syncthreads();

    for (int c = 0; c < 48; c++) {
        const int buf = c & 1;
        // issue prefetch of chunk c+1 into the other buffer (before compute)
        if (c < 47) {
            const int cc = c + 1;
            const int acol = (((cc >> 4) == 2) ? 1024 : 0) + (cc & 15) * 64;
            const int bcol = cc * 64;
            const char* Ag = Ab8 + (size_t)m0 * 4096 + acol * 2;
            const char* Bg = Bb8 + (size_t)n0 * 6144 + bcol * 2;
            const uint32_t nb = (uint32_t)((buf ^ 1) * 16384);
#pragma unroll
            for (int l = 0; l < 4; l++) {
                int r = lr + l * 32;
                uint32_t so = (uint32_t)((r * 8 + (lc ^ (r & 7))) << 4);
                CP_ASYNC16(sbase + nb + so,         Ag + (size_t)r * 4096 + lc * 16);
                CP_ASYNC16(sbase + 32768 + nb + so, Bg + (size_t)r * 6144 + lc * 16);
            }
            CP_COMMIT();
        }

        const uint32_t Abuf = sbase + buf * 16384;
        const uint32_t Bbuf = sbase + 32768 + buf * 16384;
#pragma unroll
        for (int ks = 0; ks < 4; ks++) {
            uint32_t af[2][4], bf[8][2];
#pragma unroll
            for (int mi = 0; mi < 2; mi++) {
                int row = warp_m * 32 + mi * 16 + (lane & 15);
                int c16 = 2 * ks + (lane >> 4);
                ldsm4(Abuf + ((row * 8 + (c16 ^ (row & 7))) << 4), af[mi]);
            }
#pragma unroll
            for (int nt = 0; nt < 4; nt++) {
                int row = warp_n * 64 + nt * 16 + (lane & 7) + ((lane >> 4) & 1) * 8;
                int c16 = 2 * ks + ((lane >> 3) & 1);
                uint32_t t[4];
                ldsm4(Bbuf + ((row * 8 + (c16 ^ (row & 7))) << 4), t);
                bf[nt * 2][0] = t[0]; bf[nt * 2][1] = t[1];
                bf[nt * 2 + 1][0] = t[2]; bf[nt * 2 + 1][1] = t[3];
            }
#pragma unroll
            for (int mi = 0; mi < 2; mi++)
#pragma unroll
                for (int ni = 0; ni < 8; ni++)
                    mma16816(acc[mi][ni], af[mi], bf[ni]);
        }

        if (c < 47) CP_WAIT0();
        __syncthreads();
    }

    // ---- epilogue ----
    const int em0 = m0 + warp_m * 32;
    const int en0 = n0 + warp_n * 64;
    const int er = lane >> 2, ec = (lane & 3) * 2;
#pragma unroll
    for (int mi = 0; mi < 2; mi++) {
#pragma unroll
        for (int h2 = 0; h2 < 2; h2++) {
            const int m = em0 + mi * 16 + er + h2 * 8;
            if (EPI == 0) {
                float* row = Oq + (size_t)m * EMB + en0 + ec;
#pragma unroll
                for (int ni = 0; ni < 8; ni++) {
                    float2 v2 = make_float2(acc[mi][ni][h2 * 2], acc[mi][ni][h2 * 2 + 1]);
                    *(float2*)(row + ni * 8) = v2;
                }
            } else {
                const int bb = m >> 13, nn = m & 8191;
                const int h = en0 >> 6;                 // 64-wide slab: single head
                float* base = Oq + ((size_t)(bb * HEADS + h) * NSEQ + nn) * DHEAD;
                const int d0 = (en0 & 63) + ec;
#pragma unroll
                for (int ni = 0; ni < 8; ni++) {
                    float a0 = acc[mi][ni][h2 * 2], a1 = acc[mi][ni][h2 * 2 + 1];
                    float2 v2;
                    v2.x = a0 / (1.f + expf(-a0));
                    v2.y = a1 / (1.f + expf(-a1));
                    *(float2*)(base + d0 + ni * 8) = v2;
                }
            }
        }
    }
}

// =====================================================================
// FFMA SGEMM (gate path N=1024 K=64, EPI 2 = sigmoid store)
// =====================================================================
template<int EPI>
__global__ void __launch_bounds__(256) sgemm_kernel(
    const float* __restrict__ A,
    const float* __restrict__ B0,
    float* __restrict__ O0,
    int M, int N, int K)
{
    const float* B = B0;
    float* O = O0;

    __shared__ float As[2][16][128];
    __shared__ float Bs[2][16][128];

    const int tid = threadIdx.x;
    const int tx = tid & 15, ty = tid >> 4;
    const int m0 = blockIdx.y * 128, n0 = blockIdx.x * 128;

    const int lin1 = tid + 256;
    const int ra0 = tid  >> 2, ca0 = (tid  & 3) << 2;
    const int ra1 = lin1 >> 2, ca1 = (lin1 & 3) << 2;
    const int rb0 = tid  >> 5, cb0 = (tid  & 31) << 2;
    const int rb1 = lin1 >> 5, cb1 = (lin1 & 31) << 2;

    const float* Arow0 = A + (size_t)(m0 + ra0) * K;
    const float* Arow1 = A + (size_t)(m0 + ra1) * K;
    const float* Bp0   = B + (size_t)rb0 * N + n0 + cb0;
    const float* Bp1   = B + (size_t)rb1 * N + n0 + cb1;

    float acc[8][8];
#pragma unroll
    for (int i = 0; i < 8; i++)
#pragma unroll
        for (int j = 0; j < 8; j++) acc[i][j] = 0.f;

    {
        float4 a0 = *(const float4*)(Arow0 + ca0);
        float4 a1 = *(const float4*)(Arow1 + ca1);
        float4 b0 = *(const float4*)(Bp0);
        float4 b1 = *(const float4*)(Bp1);
        As[0][ca0 + 0][ra0] = a0.x; As[0][ca0 + 1][ra0] = a0.y;
        As[0][ca0 + 2][ra0] = a0.z; As[0][ca0 + 3][ra0] = a0.w;
        As[0][ca1 + 0][ra1] = a1.x; As[0][ca1 + 1][ra1] = a1.y;
        As[0][ca1 + 2][ra1] = a1.z; As[0][ca1 + 3][ra1] = a1.w;
        *(float4*)(&Bs[0][rb0][cb0]) = b0;
        *(float4*)(&Bs[0][rb1][cb1]) = b1;
    }
    __syncthreads();

    for (int k0 = 0; k0 < K; k0 += 16) {
        const int cur = (k0 >> 4) & 1, nxt = cur ^ 1;
        const bool has_next = (k0 + 16) < K;

        float4 na0, na1, nb0, nb1;
        if (has_next) {
            na0 = *(const float4*)(Arow0 + k0 + 16 + ca0);
            na1 = *(const float4*)(Arow1 + k0 + 16 + ca1);
            nb0 = *(const float4*)(Bp0 + (size_t)(k0 + 16) * N);
            nb1 = *(const float4*)(Bp1 + (size_t)(k0 + 16) * N);
        }

#pragma unroll
        for (int kk = 0; kk < 16; kk++) {
            float a[8], b[8];
            *(float4*)(a)     = *(float4*)(&As[cur][kk][ty * 8]);
            *(float4*)(a + 4) = *(float4*)(&As[cur][kk][ty * 8 + 4]);
            *(float4*)(b)     = *(float4*)(&Bs[cur][kk][tx * 8]);
            *(float4*)(b + 4) = *(float4*)(&Bs[cur][kk][tx * 8 + 4]);
#pragma unroll
            for (int i = 0; i < 8; i++)
#pragma unroll
                for (int j = 0; j < 8; j++)
                    acc[i][j] = fmaf(a[i], b[j], acc[i][j]);
        }

        if (has_next) {
            As[nxt][ca0 + 0][ra0] = na0.x; As[nxt][ca0 + 1][ra0] = na0.y;
            As[nxt][ca0 + 2][ra0] = na0.z; As[nxt][ca0 + 3][ra0] = na0.w;
            As[nxt][ca1 + 0][ra1] = na1.x; As[nxt][ca1 + 1][ra1] = na1.y;
            As[nxt][ca1 + 2][ra1] = na1.z; As[nxt][ca1 + 3][ra1] = na1.w;
            *(float4*)(&Bs[nxt][rb0][cb0]) = nb0;
            *(float4*)(&Bs[nxt][rb1][cb1]) = nb1;
            __syncthreads();
        }
    }

    if (EPI == 2) {
#pragma unroll
        for (int i = 0; i < 8; i++) {
            float v[8];
#pragma unroll
            for (int j = 0; j < 8; j++) v[j] = 1.f / (1.f + expf(-acc[i][j]));
            size_t row = (size_t)(m0 + ty * 8 + i) * N + n0 + tx * 8;
            *(float4*)(O + row)     = make_float4(v[0], v[1], v[2], v[3]);
            *(float4*)(O + row + 4) = make_float4(v[4], v[5], v[6], v[7]);
        }
    } else {
#pragma unroll
        for (int i = 0; i < 8; i++) {
            size_t row = (size_t)(m0 + ty * 8 + i) * N + n0 + tx * 8;
            *(float4*)(O + row)     = make_float4(acc[i][0], acc[i][1], acc[i][2], acc[i][3]);
            *(float4*)(O + row + 4) = make_float4(acc[i][4], acc[i][5], acc[i][6], acc[i][7]);
        }
    }
}

// =====================================================================
// Phase A: per-chunk KV outer product
// =====================================================================
__global__ void __launch_bounds__(256) chunk_kv_kernel()
{
    const int c = blockIdx.x, h = blockIdx.y, b = blockIdx.z;
    const int bh = b * HEADS + h;
    const float s = slope_s(h);
    const float* Kp = g_k + ((size_t)bh * NSEQ + (size_t)c * CHUNK) * DHEAD;
    const float* Vp = g_v + ((size_t)bh * NSEQ + (size_t)c * CHUNK) * DHEAD;

    __shared__ float Ks[64][64];
    __shared__ float Vs[64][64];

    const int tid = threadIdx.x;
    const int et = tid & 15, dt = tid >> 4;

    float acc[4][4];
#pragma unroll
    for (int a = 0; a < 4; a++)
#pragma unroll
        for (int e = 0; e < 4; e++) acc[a][e] = 0.f;

    for (int half = 0; half < 2; half++) {
#pragma unroll
        for (int l = 0; l < 4; l++) {
            int lin = tid + l * 256;
            int r = lin >> 4, c4 = (lin & 15) << 2;
            int row = half * 64 + r;
            float lam = expf(-s * (float)(CHUNK - 1 - row));
            float4 kv4 = *(const float4*)(Kp + (size_t)row * DHEAD + c4);
            kv4.x *= lam; kv4.y *= lam; kv4.z *= lam; kv4.w *= lam;
            *(float4*)(&Ks[r][c4]) = kv4;
            *(float4*)(&Vs[r][c4]) = *(const float4*)(Vp + (size_t)row * DHEAD + c4);
        }
        __syncthreads();
#pragma unroll 16
        for (int i = 0; i < 64; i++) {
            float kk[4], vv[4];
            *(float4*)kk = *(float4*)(&Ks[i][dt * 4]);
            *(float4*)vv = *(float4*)(&Vs[i][et * 4]);
#pragma unroll
            for (int a = 0; a < 4; a++)
#pragma unroll
                for (int e = 0; e < 4; e++)
                    acc[a][e] = fmaf(kk[a], vv[e], acc[a][e]);
        }
        __syncthreads();
    }

    float* out = g_kvch + ((size_t)bh * NCHUNK + c) * (DHEAD * DHEAD);
#pragma unroll
    for (int a = 0; a < 4; a++)
        *(float4*)(out + (size_t)(dt * 4 + a) * DHEAD + et * 4) =
            make_float4(acc[a][0], acc[a][1], acc[a][2], acc[a][3]);
}

// =====================================================================
// Phase B: exclusive prefix scan over chunks of the 64x64 KV state.
// =====================================================================
__global__ void __launch_bounds__(256) scan_kv_kernel()
{
    const int bh = blockIdx.x;
    const int h = bh & (HEADS - 1);
    const float s = slope_s(h);
    const float lamc = expf(-s * (float)CHUNK);
    const int tid = threadIdx.x;

    float st[16];
#pragma unroll
    for (int j = 0; j < 16; j++) st[j] = 0.f;

    for (int c = 0; c < NCHUNK; c++) {
        size_t base = ((size_t)bh * NCHUNK + c) * (DHEAD * DHEAD);
#pragma unroll
        for (int j = 0; j < 16; j++) {
            g_kvpre[base + j * 256 + tid] = st[j];
            st[j] = fmaf(lamc, st[j], g_kvch[base + j * 256 + tid]);
        }
    }
}

// =====================================================================
// Phase C: per-chunk output.  Ss rows padded to 132 floats (528B) to
// break the 16-way bank conflict on score stores.
// =====================================================================
#define SS_STRIDE 132
#define CO_SMEM_FLOATS 37512
__global__ void __launch_bounds__(256) chunk_out_kernel()
{
    extern __shared__ float sm[];
    float* Qt  = sm;            // [64][128]
    float* KU  = sm + 8192;     // Kt [64][128] / Vs [128][64]
    float* Ss  = sm + 16384;    // [128][SS_STRIDE] transposed scores
    float* KVp = sm + 16384 + 128 * SS_STRIDE;   // [64*64]
    float* dec = KVp + 4096;    // [132]

    const int c = blockIdx.x, h = blockIdx.y, b = blockIdx.z;
    const int bh = b * HEADS + h;
    const float s = slope_s(h);
    const int tid = threadIdx.x;

    const float* Qp = g_q + ((size_t)bh * NSEQ + (size_t)c * CHUNK) * DHEAD;
    const float* Kp = g_k + ((size_t)bh * NSEQ + (size_t)c * CHUNK) * DHEAD;
    const float* Vp = g_v + ((size_t)bh * NSEQ + (size_t)c * CHUNK) * DHEAD;
    const float* KVg = g_kvpre + ((size_t)bh * NCHUNK + c) * (DHEAD * DHEAD);

    if (tid < 132) dec[tid] = expf(-s * (float)tid);

#pragma unroll
    for (int l = 0; l < 8; l++) {
        int lin = tid + l * 256;
        int r = lin >> 4, c4 = (lin & 15) << 2;
        float4 qv = *(const float4*)(Qp + (size_t)r * DHEAD + c4);
        Qt[(c4 + 0) * 128 + r] = qv.x; Qt[(c4 + 1) * 128 + r] = qv.y;
        Qt[(c4 + 2) * 128 + r] = qv.z; Qt[(c4 + 3) * 128 + r] = qv.w;
        float4 kv = *(const float4*)(Kp + (size_t)r * DHEAD + c4);
        KU[(c4 + 0) * 128 + r] = kv.x; KU[(c4 + 1) * 128 + r] = kv.y;
        KU[(c4 + 2) * 128 + r] = kv.z; KU[(c4 + 3) * 128 + r] = kv.w;
    }
#pragma unroll
    for (int l = 0; l < 16; l++) KVp[tid + l * 256] = KVg[tid + l * 256];
    __syncthreads();

    {
        const int tx = tid & 15, ty = tid >> 4;
        const int i0 = ty * 8, j0 = tx * 8;
        float acc[8][8];
#pragma unroll
        for (int i = 0; i < 8; i++)
#pragma unroll
            for (int j = 0; j < 8; j++) acc[i][j] = 0.f;

#pragma unroll 8
        for (int d = 0; d < 64; d++) {
            float qa[8], kb[8];
            *(float4*)(qa)     = *(float4*)(&Qt[d * 128 + i0]);
            *(float4*)(qa + 4) = *(float4*)(&Qt[d * 128 + i0 + 4]);
            *(float4*)(kb)     = *(float4*)(&KU[d * 128 + j0]);
            *(float4*)(kb + 4) = *(float4*)(&KU[d * 128 + j0 + 4]);
#pragma unroll
            for (int ii = 0; ii < 8; ii++)
#pragma unroll
                for (int jj = 0; jj < 8; jj++)
                    acc[ii][jj] = fmaf(qa[ii], kb[jj], acc[ii][jj]);
        }
        __syncthreads();

#pragma unroll
        for (int jj = 0; jj < 8; jj++) {
            int j = j0 + jj;
            float v[8];
#pragma unroll
            for (int ii = 0; ii < 8; ii++) {
                int dlt = (i0 + ii) - j;
                v[ii] = (dlt >= 0) ? acc[ii][jj] * dec[dlt] : 0.f;
            }
            *(float4*)(&Ss[j * SS_STRIDE + i0])     = make_float4(v[0], v[1], v[2], v[3]);
            *(float4*)(&Ss[j * SS_STRIDE + i0 + 4]) = make_float4(v[4], v[5], v[6], v[7]);
        }
#pragma unroll
        for (int l = 0; l < 8; l++) {
            int lin = tid + l * 256;
            int r = lin >> 4, c4 = (lin & 15) << 2;
            *(float4*)(&KU[r * 64 + c4]) =
                *(const float4*)(Vp + (size_t)r * DHEAD + c4);
        }
        __syncthreads();
    }

    {
        const int i0 = (tid >> 4) * 8;
        const int e0 = (tid & 15) * 4;
        float acc[8][4], ac2[8][4];
#pragma unroll
        for (int i = 0; i < 8; i++)
#pragma unroll
            for (int e = 0; e < 4; e++) { acc[i][e] = 0.f; ac2[i][e] = 0.f; }

#pragma unroll 8
        for (int j = 0; j < 128; j++) {
            float sv[8], vv[4];
            *(float4*)(sv)     = *(float4*)(&Ss[j * SS_STRIDE + i0]);
            *(float4*)(sv + 4) = *(float4*)(&Ss[j * SS_STRIDE + i0 + 4]);
            *(float4*)(vv)     = *(float4*)(&KU[j * 64 + e0]);
#pragma unroll
            for (int ii = 0; ii < 8; ii++)
#pragma unroll
                for (int ee = 0; ee < 4; ee++)
                    acc[ii][ee] = fmaf(sv[ii], vv[ee], acc[ii][ee]);
        }
#pragma unroll 8
        for (int d = 0; d < 64; d++) {
            float qa[8], kv[4];
            *(float4*)(qa)     = *(float4*)(&Qt[d * 128 + i0]);
            *(float4*)(qa + 4) = *(float4*)(&Qt[d * 128 + i0 + 4]);
            *(float4*)(kv)     = *(float4*)(&KVp[d * 64 + e0]);
#pragma unroll
            for (int ii = 0; ii < 8; ii++)
#pragma unroll
                for (int ee = 0; ee < 4; ee++)
                    ac2[ii][ee] = fmaf(qa[ii], kv[ee], ac2[ii][ee]);
        }
#pragma unroll
        for (int ii = 0; ii < 8; ii++) {
            int i = i0 + ii;
            float lq = dec[i + 1];
            int m = b * NSEQ + c * CHUNK + i;
            size_t off = (size_t)m * EMB + h * DHEAD + e0;
            float4 r4;
            r4.x = fmaf(lq, ac2[ii][0], acc[ii][0]);
            r4.y = fmaf(lq, ac2[ii][1], acc[ii][1]);
            r4.z = fmaf(lq, ac2[ii][2], acc[ii][2]);
            r4.w = fmaf(lq, ac2[ii][3], acc[ii][3]);
            *(float4*)(g_o + off) = r4;
        }
    }
}

// =====================================================================
// g1 = x @ Wg1  ([16384,1024] @ [1024,64])
// =====================================================================
__global__ void __launch_bounds__(256) gemm_g1_kernel(
    const float* __restrict__ A, const float* __restrict__ W)
{
    __shared__ float At[16][128];
    __shared__ float Ws[16][64];
    const int tid = threadIdx.x;
    const int tx = tid & 15, ty = tid >> 4;
    const int m0 = blockIdx.x * 128;

    float acc[8][4];
#pragma unroll
    for (int i = 0; i < 8; i++)
#pragma unroll
        for (int j = 0; j < 4; j++) acc[i][j] = 0.f;

    for (int k0 = 0; k0 < EMB; k0 += 16) {
#pragma unroll
        for (int l = 0; l < 2; l++) {
            int lin = tid + l * 256;
            int r = lin >> 2, c = (lin & 3) << 2;
            float4 av = *(const float4*)(A + (size_t)(m0 + r) * EMB + k0 + c);
            At[c + 0][r] = av.x; At[c + 1][r] = av.y;
            At[c + 2][r] = av.z; At[c + 3][r] = av.w;
        }
        {
            int r = tid >> 4, c4 = (tid & 15) << 2;
            *(float4*)(&Ws[r][c4]) = *(const float4*)(W + (size_t)(k0 + r) * DHEAD + c4);
        }
        __syncthreads();
#pragma unroll
        for (int kk = 0; kk < 16; kk++) {
            float a[8], w[4];
            *(float4*)(a)     = *(float4*)(&At[kk][ty * 8]);
            *(float4*)(a + 4) = *(float4*)(&At[kk][ty * 8 + 4]);
            *(float4*)(w)     = *(float4*)(&Ws[kk][tx * 4]);
#pragma unroll
            for (int i = 0; i < 8; i++)
#pragma unroll
                for (int j = 0; j < 4; j++)
                    acc[i][j] = fmaf(a[i], w[j], acc[i][j]);
        }
        __syncthreads();
    }
#pragma unroll
    for (int i = 0; i < 8; i++)
        *(float4*)(g_g1 + (size_t)(m0 + ty * 8 + i) * DHEAD + tx * 4) =
            make_float4(acc[i][0], acc[i][1], acc[i][2], acc[i][3]);
}

// =====================================================================
// LayerNorm(o) * gate -> split bf16 hi/lo into g_te (feeds Wo GEMM)
// =====================================================================
__global__ void __launch_bounds__(256) ln_gate_kernel(
    const float* __restrict__ gamma, const float* __restrict__ beta)
{
    const int r = blockIdx.x;
    const int tid = threadIdx.x;
    const float4 v = *(const float4*)(g_o + (size_t)r * EMB + tid * 4);
    float sum = v.x + v.y + v.z + v.w;
    float sq  = v.x * v.x + v.y * v.y + v.z * v.z + v.w * v.w;
#pragma unroll
    for (int o = 16; o > 0; o >>= 1) {
        sum += __shfl_xor_sync(0xFFFFFFFFu, sum, o);
        sq  += __shfl_xor_sync(0xFFFFFFFFu, sq, o);
    }
    __shared__ float rs_[8], rq_[8];
    __shared__ float mu_s, rstd_s;
    int w = tid >> 5;
    if ((tid & 31) == 0) { rs_[w] = sum; rq_[w] = sq; }
    __syncthreads();
    if (tid == 0) {
        float S = 0.f, Q = 0.f;
#pragma unroll
        for (int i = 0; i < 8; i++) { S += rs_[i]; Q += rq_[i]; }
        float mu = S * (1.f / EMB);
        float var = Q * (1.f / EMB) - mu * mu;
        mu_s = mu;
        rstd_s = rsqrtf(var + 1e-5f);
    }
    __syncthreads();
    const float mu = mu_s, rstd = rstd_s;
    const float4 g  = *(const float4*)(gamma + tid * 4);
    const float4 be = *(const float4*)(beta + tid * 4);
    const float4 gt = *(const float4*)(g_gate + (size_t)r * EMB + tid * 4);
    float t0 = ((v.x - mu) * rstd * g.x + be.x) * gt.x;
    float t1 = ((v.y - mu) * rstd * g.y + be.y) * gt.y;
    float t2 = ((v.z - mu) * rstd * g.z + be.z) * gt.z;
    float t3 = ((v.w - mu) * rstd * g.w + be.w) * gt.w;
    __nv_bfloat16 h[4], l[4];
    split_bf16(t0, h[0], l[0]); split_bf16(t1, h[1], l[1]);
    split_bf16(t2, h[2], l[2]); split_bf16(t3, h[3], l[3]);
    *(uint2*)(g_te + (size_t)r * 2048 + tid * 4)        = *(uint2*)h;
    *(uint2*)(g_te + (size_t)r * 2048 + 1024 + tid * 4) = *(uint2*)l;
}

// =====================================================================
extern "C" void kernel_launch(void* const* d_in, const int* in_sizes, int n_in,
                              void* d_out, int out_size)
{
    const float* x     = (const float*)d_in[0];
    const float* Wq    = (const float*)d_in[1];
    const float* Wk    = (const float*)d_in[2];
    const float* Wv    = (const float*)d_in[3];
    const float* Wo    = (const float*)d_in[4];
    const float* gamma = (const float*)d_in[5];
    const float* beta  = (const float*)d_in[6];
    const float* Wg1   = (const float*)d_in[7];
    const float* Wg2   = (const float*)d_in[8];
    float* out = (float*)d_out;

    float *q, *k, *v, *g1p, *gatep;
    __nv_bfloat16 *xep, *tep, *wep;
    cudaGetSymbolAddress((void**)&q,     g_q);
    cudaGetSymbolAddress((void**)&k,     g_k);
    cudaGetSymbolAddress((void**)&v,     g_v);
    cudaGetSymbolAddress((void**)&g1p,   g_g1);
    cudaGetSymbolAddress((void**)&gatep, g_gate);
    cudaGetSymbolAddress((void**)&xep,   g_xe);
    cudaGetSymbolAddress((void**)&tep,   g_te);
    cudaGetSymbolAddress((void**)&wep,   g_we);

    cudaFuncSetAttribute(chunk_out_kernel,
                         cudaFuncAttributeMaxDynamicSharedMemorySize,
                         CO_SMEM_FLOATS * 4);
    cudaFuncSetAttribute(hgemm_kernel<0>,
                         cudaFuncAttributeMaxDynamicSharedMemorySize, HG_SMEM);
    cudaFuncSetAttribute(hgemm_kernel<1>,
                         cudaFuncAttributeMaxDynamicSharedMemorySize, HG_SMEM);

    // 0. split conversions
    conv_x_kernel<<<MROWS, 256>>>(x);
    conv_w_kernel<<<dim3(32, 32, 4), 256>>>(Wq, Wk, Wv, Wo);

    // 1. q/k/v = silu(x @ W{q,k,v}) via HMMA, scattered to [b,h,n,d]
    hgemm_kernel<1><<<dim3(8, 128, 3), 256, HG_SMEM>>>(xep, wep, q, k, v);

    // 2. attention phases
    chunk_kv_kernel<<<dim3(NCHUNK, HEADS, BATCH), 256>>>();
    scan_kv_kernel<<<BATCH * HEADS, 256>>>();
    chunk_out_kernel<<<dim3(NCHUNK, HEADS, BATCH), 256, CO_SMEM_FLOATS * 4>>>();

    // 3. gate path (small, FFMA)
    gemm_g1_kernel<<<MROWS / 128, 256>>>(x, Wg1);
    sgemm_kernel<2><<<dim3(EMB / 128, MROWS / 128, 1), 256>>>(
        g1p, Wg2, gatep, MROWS, EMB, DHEAD);

    // 4. layernorm * gate -> t (hi/lo split)
    ln_gate_kernel<<<MROWS, 256>>>(gamma, beta);

    // 5. out = t @ Wo via HMMA
    hgemm_kernel<0><<<dim3(8, 128, 1), 256, HG_SMEM>>>(
        tep, wep + (size_t)3 * EMB * KEXT, out, nullptr, nullptr);
}